// round 11
// baseline (speedup 1.0000x reference)
#include <cuda_runtime.h>
#include <math.h>

// Problem constants
#define BB 16
#define TT 32
#define HH 40
#define WW 40
#define FF 40
#define NG 160              // 4*F gate channels
#define NT 256              // threads per block
#define SEQN (BB*TT*HH*WW*FF)
#define STN  (BB*HH*WW*FF)

// ---------------------------------------------------------------------------
// Static device scratch.
// ---------------------------------------------------------------------------
__device__ float g_seq[4][SEQN];
__device__ float g_h[4][2][STN];
__device__ float g_c[4][STN];

__device__ __forceinline__ float hsig(float x) {
    return fminf(fmaxf(0.2f * x + 0.5f, 0.0f), 1.0f);
}

__device__ __forceinline__ unsigned long long packf2(float lo, float hi) {
    unsigned long long r;
    asm("mov.b64 %0, {%1, %2};" : "=l"(r) : "f"(lo), "f"(hi));
    return r;
}
__device__ __forceinline__ float2 unpackf2(unsigned long long v) {
    float2 r;
    asm("mov.b64 {%0, %1}, %2;" : "=f"(r.x), "=f"(r.y) : "l"(v));
    return r;
}
__device__ __forceinline__ void fma2(unsigned long long& d,
                                     unsigned long long a, unsigned long long b) {
    asm("fma.rn.f32x2 %0, %1, %2, %0;" : "+l"(d) : "l"(a), "l"(b));
}

// ---------------------------------------------------------------------------
// One ConvLSTM timestep tile for one (layer, t): block = one image row (b,y).
// GEMM: M=40 px, N=160 gates, K=9*C2P (x/h merged, zero-padded).
// 256 threads: warp = 5 pixels, lane = 5 channels (n, n+32, ..., n+128).
// f32x2 accumulators packed over (even k, odd k) -> zero marshalling MOVs:
//   A: LDS.64 of contiguous (k,k+1) from sIn (broadcast across lanes)
//   B: LDS.64 of k-interleaved weight pairs (coalesced)
// SMEM: sIn[3][42][C2P] + sW2[C2P/2][160] float2.  CIN=40: 91520 B -> 2 CTA/SM.
// ---------------------------------------------------------------------------
template <int CIN>
__device__ __forceinline__ void lstm_tile(
    const float* __restrict__ xseq,   // [B,T,H,W,CIN]
    const float* __restrict__ hin,    // [B,H,W,F]
    float* __restrict__ hout,         // [B,H,W,F]
    float* __restrict__ cst,          // [B,H,W,F] in/out
    const float* __restrict__ Wx,     // [9,CIN,160]
    const float* __restrict__ Wh,     // [9,F,160]
    const float* __restrict__ bias,   // [160]
    const float* __restrict__ bng, const float* __restrict__ bnb,
    const float* __restrict__ bnm, const float* __restrict__ bnv,
    float* __restrict__ yout,         // [B,T,H,W,F]
    int t, int first)
{
    constexpr int HOFF  = (CIN + 3) & ~3;   // h channels start (4 or 40)
    constexpr int C2P   = HOFF + FF;        // padded concat channels (44 or 80)
    constexpr int INROW = 42;               // 40 + halo
    constexpr int KP    = C2P / 2;          // k-pairs per tap (22 or 40)

    extern __shared__ float smem[];
    float* sIn = smem;                        // [3][INROW][C2P]
    float* sWf = smem + 3 * INROW * C2P;      // [KP][160] float2 (k-interleaved)

    const int tid = threadIdx.x;
    const int y   = blockIdx.x;
    const int b   = blockIdx.y;
    const int n   = tid & 31;               // base output channel
    const int mt  = tid >> 5;               // warp id -> pixels mt*5 .. mt*5+4

    // ---- zero input tile (halo + channel padding) ----
    for (int i = tid; i < 3 * INROW * C2P; i += NT) sIn[i] = 0.0f;
    __syncthreads();

    // ---- fill x part ----
    if (CIN == 1) {
        for (int i = tid; i < 3 * WW; i += NT) {
            int r = i / WW, x = i % WW;
            int gy = y + r - 1;
            if (gy >= 0 && gy < HH)
                sIn[(r * INROW + x + 1) * C2P] =
                    xseq[((b * TT + t) * HH + gy) * WW + x];
        }
    } else {
        constexpr int NC4 = CIN / 4;
        for (int i = tid; i < 3 * WW * NC4; i += NT) {
            int c4 = i % NC4;
            int rest = i / NC4;
            int x = rest % WW, r = rest / WW;
            int gy = y + r - 1;
            if (gy >= 0 && gy < HH) {
                float4 v = *(const float4*)&xseq[(((b * TT + t) * HH + gy) * WW + x) * CIN + c4 * 4];
                *(float4*)&sIn[(r * INROW + x + 1) * C2P + c4 * 4] = v;
            }
        }
    }

    // ---- fill h part (h==0 at t==0: region stays zero) ----
    if (!first) {
        for (int i = tid; i < 3 * WW * (FF / 4); i += NT) {
            int c4 = i % (FF / 4);
            int rest = i / (FF / 4);
            int x = rest % WW, r = rest / WW;
            int gy = y + r - 1;
            if (gy >= 0 && gy < HH) {
                float4 v = *(const float4*)&hin[((b * HH + gy) * WW + x) * FF + c4 * 4];
                *(float4*)&sIn[(r * INROW + x + 1) * C2P + HOFF + c4 * 4] = v;
            }
        }
    }

    // ---- accumulators = (bias, 0): lo accumulates even k, hi odd k ----
    unsigned long long acc[5][5];
#pragma unroll
    for (int j = 0; j < 5; j++) {
        unsigned long long bp = packf2(bias[n + 32 * j], 0.0f);
#pragma unroll
        for (int i = 0; i < 5; i++) acc[i][j] = bp;
    }

    const float* wxt = Wx;
    const float* wht = Wh;

    // ---- main loop: 9 taps, merged x+h K-block per tap ----
#pragma unroll 1
    for (int tap = 0; tap < 9; ++tap) {
        const int dy = tap / 3, dx = tap % 3;

        // stage k-interleaved weight pairs for this tap (zero rows = padding)
        __syncthreads();   // previous tap's weights fully consumed
        for (int p = tid; p < KP * NG; p += NT) {
            int c  = p % NG;
            int kp = p / NG;
            int k0 = 2 * kp, k1 = 2 * kp + 1;
            float w0, w1;
            if (CIN == 40) {
                w0 = (k0 < 40) ? wxt[k0 * NG + c] : wht[(k0 - 40) * NG + c];
                w1 = (k1 < 40) ? wxt[k1 * NG + c] : wht[(k1 - 40) * NG + c];
            } else {
                w0 = (k0 < CIN) ? wxt[k0 * NG + c]
                   : (k0 >= HOFF ? wht[(k0 - HOFF) * NG + c] : 0.0f);
                w1 = (k1 < CIN) ? wxt[k1 * NG + c]
                   : (k1 >= HOFF ? wht[(k1 - HOFF) * NG + c] : 0.0f);
            }
            ((float2*)sWf)[p] = make_float2(w0, w1);
        }
        __syncthreads();

        const float* abase = sIn + (dy * INROW + dx) * C2P;
        const unsigned long long* bb =
            (const unsigned long long*)sWf + (n);

#pragma unroll 2
        for (int kp = 0; kp < KP; ++kp) {
            unsigned long long a2[5], b2[5];
#pragma unroll
            for (int i = 0; i < 5; i++)
                a2[i] = *(const unsigned long long*)(abase + (mt * 5 + i) * C2P + 2 * kp);
#pragma unroll
            for (int j = 0; j < 5; j++)
                b2[j] = bb[kp * NG + 32 * j];
#pragma unroll
            for (int i = 0; i < 5; i++)
#pragma unroll
                for (int j = 0; j < 5; j++) fma2(acc[i][j], a2[i], b2[j]);
        }

        wxt += CIN * NG;
        wht += FF * NG;
    }

    // ---- z = lo + hi into smem base (sIn/sWf dead), then gate math ----
    __syncthreads();
    float* sZ = smem;   // 40*160 floats = 25.6KB (fits in smem region)
#pragma unroll
    for (int i = 0; i < 5; i++)
#pragma unroll
        for (int j = 0; j < 5; j++) {
            float2 v = unpackf2(acc[i][j]);
            sZ[(mt * 5 + i) * NG + n + 32 * j] = v.x + v.y;
        }
    __syncthreads();

    for (int p = tid; p < WW * FF; p += NT) {
        int x = p / FF, c = p % FF;
        float zi = sZ[x * NG + c];
        float zf = sZ[x * NG + 40 + c];
        float zg = sZ[x * NG + 80 + c];
        float zo = sZ[x * NG + 120 + c];
        int off = ((b * HH + y) * WW + x) * FF + c;
        float cp = first ? 0.0f : cst[off];
        float cn = hsig(zf) * cp + hsig(zi) * tanhf(zg);
        float hn = hsig(zo) * tanhf(cn);
        cst[off]  = cn;
        hout[off] = hn;
        float s  = bng[c] * rsqrtf(bnv[c] + 1e-3f);
        float tt = bnb[c] - bnm[c] * s;
        yout[(((b * TT + t) * HH + y) * WW + x) * FF + c] = hn * s + tt;
    }
}

// ---------------------------------------------------------------------------
// Wavefront kernel: one launch covers all active (layer, t = wave - layer).
// ---------------------------------------------------------------------------
struct WaveP {
    const float* in[4];
    float*       out[4];
    const float* hin[4];
    float*       hout[4];
    float*       c[4];
    const float* Wx[4]; const float* Wh[4]; const float* bias[4];
    const float* g[4];  const float* be[4]; const float* mu[4]; const float* v[4];
    int wave, l0;
};

__global__ __launch_bounds__(NT, 2) void wave_kernel(WaveP P)
{
    const int l = P.l0 + blockIdx.z;
    const int t = P.wave - l;
    const int first = (t == 0);
    if (l == 0)
        lstm_tile<1>(P.in[0], P.hin[0], P.hout[0], P.c[0],
                     P.Wx[0], P.Wh[0], P.bias[0],
                     P.g[0], P.be[0], P.mu[0], P.v[0],
                     P.out[0], t, first);
    else
        lstm_tile<40>(P.in[l], P.hin[l], P.hout[l], P.c[l],
                      P.Wx[l], P.Wh[l], P.bias[l],
                      P.g[l], P.be[l], P.mu[l], P.v[l],
                      P.out[l], t, first);
}

// ---------------------------------------------------------------------------
// Conv3D head: 3x3x3 over (T,H,W), 40 -> 1 channel, + sigmoid.
// ---------------------------------------------------------------------------
__global__ __launch_bounds__(160) void conv3d_kernel(
    const float* __restrict__ in,   // [B,T,H,W,F]
    const float* __restrict__ w3,   // [27*F]
    const float* __restrict__ b3,   // [1]
    float* __restrict__ out)        // [B,T,H,W]
{
    extern __shared__ float smem[];
    float* sT  = smem;                 // [9][42][40]
    float* sWc = smem + 9 * 42 * 40;   // [1080]
    float* sP  = sWc + 27 * 40;        // [4][40]

    const int tid = threadIdx.x;
    const int y = blockIdx.x, t = blockIdx.y, b = blockIdx.z;

    for (int i = tid; i < 9 * 42 * 40; i += 160) sT[i] = 0.0f;
    for (int i = tid; i < 27 * 40; i += 160) sWc[i] = w3[i];
    __syncthreads();

    for (int i = tid; i < 9 * 40 * 10; i += 160) {
        int c4 = i % 10;
        int rest = i / 10;
        int x = rest % 40;
        int rr = rest / 40;            // dt*3+dy
        int dt = rr / 3, dy = rr % 3;
        int gt = t + dt - 1, gy = y + dy - 1;
        if (gt >= 0 && gt < TT && gy >= 0 && gy < HH) {
            float4 v = *(const float4*)&in[(((b * TT + gt) * HH + gy) * WW + x) * FF + c4 * 4];
            *(float4*)&sT[(rr * 42 + x + 1) * 40 + c4 * 4] = v;
        }
    }
    __syncthreads();

    const int x  = tid % 40;
    const int cg = tid / 40;
    float s = 0.0f;
#pragma unroll 1
    for (int rr = 0; rr < 9; rr++) {
#pragma unroll
        for (int dx = 0; dx < 3; dx++) {
            const float* ip = &sT[(rr * 42 + x + dx) * 40 + cg * 10];
            const float* wp = &sWc[(rr * 3 + dx) * 40 + cg * 10];
#pragma unroll
            for (int c = 0; c < 10; c++) s += ip[c] * wp[c];
        }
    }
    sP[cg * 40 + x] = s;
    __syncthreads();
    if (tid < 40) {
        float v = sP[tid] + sP[40 + tid] + sP[80 + tid] + sP[120 + tid] + b3[0];
        out[((b * TT + t) * HH + y) * WW + tid] = 1.0f / (1.0f + expf(-v));
    }
}

// ---------------------------------------------------------------------------
// kernel_launch: 35 wavefront launches + conv3d head. Graph-capturable.
// ---------------------------------------------------------------------------
extern "C" void kernel_launch(void* const* d_in, const int* in_sizes, int n_in,
                              void* d_out, int out_size)
{
    (void)in_sizes; (void)n_in; (void)out_size;

    const float* inp = (const float*)d_in[0];
    const float* W3  = (const float*)d_in[29];
    const float* b3  = (const float*)d_in[30];

    float *seqbase, *hbase, *cbase;
    cudaGetSymbolAddress((void**)&seqbase, g_seq);
    cudaGetSymbolAddress((void**)&hbase,   g_h);
    cudaGetSymbolAddress((void**)&cbase,   g_c);

    float* seqp[4];
    float* hp[4][2];
    float* cp[4];
    for (int l = 0; l < 4; l++) {
        seqp[l]  = seqbase + (size_t)l * SEQN;
        hp[l][0] = hbase + ((size_t)l * 2 + 0) * STN;
        hp[l][1] = hbase + ((size_t)l * 2 + 1) * STN;
        cp[l]    = cbase + (size_t)l * STN;
    }

    // sIn (CIN=40): 3*42*80 = 10080 floats; sW2: 40*160 float2 = 12800 floats
    const int SMEMW  = (3 * 42 * 80 + 40 * NG * 2) * 4;        // 91520 B
    const int smem3d = (9 * 42 * 40 + 27 * 40 + 4 * 40) * 4;   // 65440 B

    cudaFuncSetAttribute(wave_kernel,   cudaFuncAttributeMaxDynamicSharedMemorySize, SMEMW);
    cudaFuncSetAttribute(conv3d_kernel, cudaFuncAttributeMaxDynamicSharedMemorySize, smem3d);

    for (int wave = 0; wave < TT + 3; wave++) {
        int l0 = wave - (TT - 1); if (l0 < 0) l0 = 0;
        int l1 = wave < 3 ? wave : 3;

        WaveP P;
        for (int l = 0; l < 4; l++) {
            int t = wave - l;
            int tc = t < 0 ? 0 : (t > TT - 1 ? TT - 1 : t);
            P.in[l]   = (l == 0) ? inp : seqp[l - 1];
            P.out[l]  = seqp[l];
            P.hin[l]  = hp[l][tc & 1];
            P.hout[l] = hp[l][(tc + 1) & 1];
            P.c[l]    = cp[l];
            P.Wx[l]   = (const float*)d_in[1 + 7 * l];
            P.Wh[l]   = (const float*)d_in[2 + 7 * l];
            P.bias[l] = (const float*)d_in[3 + 7 * l];
            P.g[l]    = (const float*)d_in[4 + 7 * l];
            P.be[l]   = (const float*)d_in[5 + 7 * l];
            P.mu[l]   = (const float*)d_in[6 + 7 * l];
            P.v[l]    = (const float*)d_in[7 + 7 * l];
        }
        P.wave = wave;
        P.l0   = l0;

        wave_kernel<<<dim3(HH, BB, l1 - l0 + 1), NT, SMEMW>>>(P);
    }

    conv3d_kernel<<<dim3(HH, TT, BB), 160, smem3d>>>(seqp[3], W3, b3, (float*)d_out);
}

// round 12
// speedup vs baseline: 1.1255x; 1.1255x over previous
#include <cuda_runtime.h>
#include <math.h>

// Problem constants
#define BB 16
#define TT 32
#define HH 40
#define WW 40
#define FF 40
#define NG 160              // 4*F gate channels
#define NT 128              // threads per block
#define SEQN (BB*TT*HH*WW*FF)
#define STN  (BB*HH*WW*FF)

// ---------------------------------------------------------------------------
// Static device scratch.
// ---------------------------------------------------------------------------
__device__ float g_seq[4][SEQN];
__device__ float g_h[4][2][STN];
__device__ float g_c[4][STN];

__device__ __forceinline__ float hsig(float x) {
    return fminf(fmaxf(0.2f * x + 0.5f, 0.0f), 1.0f);
}

__device__ __forceinline__ unsigned long long packf2(float lo, float hi) {
    unsigned long long r;
    asm("mov.b64 %0, {%1, %2};" : "=l"(r) : "f"(lo), "f"(hi));
    return r;
}
__device__ __forceinline__ float2 unpackf2(unsigned long long v) {
    float2 r;
    asm("mov.b64 {%0, %1}, %2;" : "=f"(r.x), "=f"(r.y) : "l"(v));
    return r;
}
__device__ __forceinline__ void fma2(unsigned long long& d,
                                     unsigned long long a, unsigned long long b) {
    asm("fma.rn.f32x2 %0, %1, %2, %0;" : "+l"(d) : "l"(a), "l"(b));
}

// ---------------------------------------------------------------------------
// One ConvLSTM timestep tile for one (layer, t): block = one image row (b,y).
// GEMM: M=40 px, N=160 gates, K=9*C2P (x/h merged, zero-padded).
// 128 threads: warp = 10 pixels, lane = 5 channels (n, n+32, ..., n+128).
// f32x2 accumulators packed over (even k, odd k); k consumed 4 at a time:
//   A: one LDS.128 (ulonglong2) per pixel per quad  (warp-broadcast)
//   B: one LDS.128 per channel per quad  (k-quad-interleaved staging)
// -> zero marshalling MOVs, crossbar 30 cyc/warp/quad vs 200 FMA2 pipe cyc.
// SMEM (CIN=40): sIn 3*42*80*4 = 40320B + sW4 10*160*16 = 25600B -> 3 CTA/SM.
// ---------------------------------------------------------------------------
template <int CIN>
__device__ __forceinline__ void lstm_tile(
    const float* __restrict__ xseq,   // [B,T,H,W,CIN]
    const float* __restrict__ hin,    // [B,H,W,F]
    float* __restrict__ hout,         // [B,H,W,F]
    float* __restrict__ cst,          // [B,H,W,F] in/out
    const float* __restrict__ Wx,     // [9,CIN,160]
    const float* __restrict__ Wh,     // [9,F,160]
    const float* __restrict__ bias,   // [160]
    const float* __restrict__ bng, const float* __restrict__ bnb,
    const float* __restrict__ bnm, const float* __restrict__ bnv,
    float* __restrict__ yout,         // [B,T,H,W,F]
    int t, int first)
{
    constexpr int HOFF  = (CIN + 3) & ~3;   // h channels start (4 or 40)
    constexpr int C2P   = HOFF + FF;        // padded concat channels (44 or 80)
    constexpr int INROW = 42;               // 40 + halo
    constexpr int NQ    = C2P / 4;          // k-quads per tap (11 or 20)
    constexpr int CQ    = (CIN == 1) ? 11 : 10;  // staged quads per chunk

    extern __shared__ float smem[];
    float* sIn = smem;                        // [3][INROW][C2P]
    float* sW4 = smem + 3 * INROW * C2P;      // [CQ][NG] float4 (quad-interleaved)

    const int tid = threadIdx.x;
    const int y   = blockIdx.x;
    const int b   = blockIdx.y;
    const int n   = tid & 31;               // base output channel
    const int mt  = tid >> 5;               // warp -> pixels mt*10 .. mt*10+9

    // ---- zero input tile (halo + channel padding) ----
    for (int i = tid; i < 3 * INROW * C2P; i += NT) sIn[i] = 0.0f;
    __syncthreads();

    // ---- fill x part ----
    if (CIN == 1) {
        for (int i = tid; i < 3 * WW; i += NT) {
            int r = i / WW, x = i % WW;
            int gy = y + r - 1;
            if (gy >= 0 && gy < HH)
                sIn[(r * INROW + x + 1) * C2P] =
                    xseq[((b * TT + t) * HH + gy) * WW + x];
        }
    } else {
        constexpr int NC4 = CIN / 4;
        for (int i = tid; i < 3 * WW * NC4; i += NT) {
            int c4 = i % NC4;
            int rest = i / NC4;
            int x = rest % WW, r = rest / WW;
            int gy = y + r - 1;
            if (gy >= 0 && gy < HH) {
                float4 v = *(const float4*)&xseq[(((b * TT + t) * HH + gy) * WW + x) * CIN + c4 * 4];
                *(float4*)&sIn[(r * INROW + x + 1) * C2P + c4 * 4] = v;
            }
        }
    }

    // ---- fill h part (h==0 at t==0: region stays zero) ----
    if (!first) {
        for (int i = tid; i < 3 * WW * (FF / 4); i += NT) {
            int c4 = i % (FF / 4);
            int rest = i / (FF / 4);
            int x = rest % WW, r = rest / WW;
            int gy = y + r - 1;
            if (gy >= 0 && gy < HH) {
                float4 v = *(const float4*)&hin[((b * HH + gy) * WW + x) * FF + c4 * 4];
                *(float4*)&sIn[(r * INROW + x + 1) * C2P + HOFF + c4 * 4] = v;
            }
        }
    }

    // ---- accumulators = (bias, 0): lo = even-k sum, hi = odd-k sum ----
    unsigned long long acc[10][5];
#pragma unroll
    for (int j = 0; j < 5; j++) {
        unsigned long long bp = packf2(bias[n + 32 * j], 0.0f);
#pragma unroll
        for (int i = 0; i < 10; i++) acc[i][j] = bp;
    }

    const float* wxt = Wx;
    const float* wht = Wh;

    // ---- main loop: 9 taps, merged x+h K-block, staged CQ quads at a time --
#pragma unroll 1
    for (int tap = 0; tap < 9; ++tap) {
        const int dy = tap / 3, dx = tap % 3;

#pragma unroll 1
        for (int q0 = 0; q0 < NQ; q0 += CQ) {
            const int nq = (NQ - q0 < CQ) ? (NQ - q0) : CQ;

            // stage quad-interleaved weights (zero rows = channel padding)
            __syncthreads();   // previous chunk fully consumed
            for (int p = tid; p < nq * NG; p += NT) {
                int c = p % NG;
                int q = p / NG;
                int k = (q0 + q) * 4;
                float w[4];
#pragma unroll
                for (int u = 0; u < 4; u++) {
                    int kk = k + u;
                    if (CIN == 40)
                        w[u] = (kk < 40) ? wxt[kk * NG + c] : wht[(kk - 40) * NG + c];
                    else
                        w[u] = (kk < CIN) ? wxt[kk * NG + c]
                             : (kk >= HOFF ? wht[(kk - HOFF) * NG + c] : 0.0f);
                }
                ((float4*)sW4)[p] = make_float4(w[0], w[1], w[2], w[3]);
            }
            __syncthreads();

            const float* abase = sIn + (dy * INROW + dx) * C2P + q0 * 4
                               + mt * 10 * C2P;
            const ulonglong2* bb = (const ulonglong2*)sW4 + n;

#pragma unroll 1
            for (int q = 0; q < nq; ++q) {
                ulonglong2 b2[5];
#pragma unroll
                for (int j = 0; j < 5; j++)
                    b2[j] = bb[q * NG + 32 * j];

#pragma unroll
                for (int half = 0; half < 2; ++half) {
                    ulonglong2 a2[5];
#pragma unroll
                    for (int i = 0; i < 5; i++)
                        a2[i] = *(const ulonglong2*)(abase + (half * 5 + i) * C2P + 4 * q);
#pragma unroll
                    for (int i = 0; i < 5; i++) {
#pragma unroll
                        for (int j = 0; j < 5; j++)
                            fma2(acc[half * 5 + i][j], a2[i].x, b2[j].x);
#pragma unroll
                        for (int j = 0; j < 5; j++)
                            fma2(acc[half * 5 + i][j], a2[i].y, b2[j].y);
                    }
                }
            }
        }

        wxt += CIN * NG;
        wht += FF * NG;
    }

    // ---- z = lo + hi into smem base (sIn/sW4 dead), then gate math ----
    __syncthreads();
    float* sZ = smem;   // 40*160 floats = 25.6KB
#pragma unroll
    for (int i = 0; i < 10; i++)
#pragma unroll
        for (int j = 0; j < 5; j++) {
            float2 v = unpackf2(acc[i][j]);
            sZ[(mt * 10 + i) * NG + n + 32 * j] = v.x + v.y;
        }
    __syncthreads();

    for (int p = tid; p < WW * FF; p += NT) {
        int x = p / FF, c = p % FF;
        float zi = sZ[x * NG + c];
        float zf = sZ[x * NG + 40 + c];
        float zg = sZ[x * NG + 80 + c];
        float zo = sZ[x * NG + 120 + c];
        int off = ((b * HH + y) * WW + x) * FF + c;
        float cp = first ? 0.0f : cst[off];
        float cn = hsig(zf) * cp + hsig(zi) * tanhf(zg);
        float hn = hsig(zo) * tanhf(cn);
        cst[off]  = cn;
        hout[off] = hn;
        float s  = bng[c] * rsqrtf(bnv[c] + 1e-3f);
        float tt = bnb[c] - bnm[c] * s;
        yout[(((b * TT + t) * HH + y) * WW + x) * FF + c] = hn * s + tt;
    }
}

// ---------------------------------------------------------------------------
// Wavefront kernel: one launch covers all active (layer, t = wave - layer).
// ---------------------------------------------------------------------------
struct WaveP {
    const float* in[4];
    float*       out[4];
    const float* hin[4];
    float*       hout[4];
    float*       c[4];
    const float* Wx[4]; const float* Wh[4]; const float* bias[4];
    const float* g[4];  const float* be[4]; const float* mu[4]; const float* v[4];
    int wave, l0;
};

__global__ __launch_bounds__(NT, 3) void wave_kernel(WaveP P)
{
    const int l = P.l0 + blockIdx.z;
    const int t = P.wave - l;
    const int first = (t == 0);
    if (l == 0)
        lstm_tile<1>(P.in[0], P.hin[0], P.hout[0], P.c[0],
                     P.Wx[0], P.Wh[0], P.bias[0],
                     P.g[0], P.be[0], P.mu[0], P.v[0],
                     P.out[0], t, first);
    else
        lstm_tile<40>(P.in[l], P.hin[l], P.hout[l], P.c[l],
                      P.Wx[l], P.Wh[l], P.bias[l],
                      P.g[l], P.be[l], P.mu[l], P.v[l],
                      P.out[l], t, first);
}

// ---------------------------------------------------------------------------
// Conv3D head: 3x3x3 over (T,H,W), 40 -> 1 channel, + sigmoid.
// ---------------------------------------------------------------------------
__global__ __launch_bounds__(160) void conv3d_kernel(
    const float* __restrict__ in,   // [B,T,H,W,F]
    const float* __restrict__ w3,   // [27*F]
    const float* __restrict__ b3,   // [1]
    float* __restrict__ out)        // [B,T,H,W]
{
    extern __shared__ float smem[];
    float* sT  = smem;                 // [9][42][40]
    float* sWc = smem + 9 * 42 * 40;   // [1080]
    float* sP  = sWc + 27 * 40;        // [4][40]

    const int tid = threadIdx.x;
    const int y = blockIdx.x, t = blockIdx.y, b = blockIdx.z;

    for (int i = tid; i < 9 * 42 * 40; i += 160) sT[i] = 0.0f;
    for (int i = tid; i < 27 * 40; i += 160) sWc[i] = w3[i];
    __syncthreads();

    for (int i = tid; i < 9 * 40 * 10; i += 160) {
        int c4 = i % 10;
        int rest = i / 10;
        int x = rest % 40;
        int rr = rest / 40;            // dt*3+dy
        int dt = rr / 3, dy = rr % 3;
        int gt = t + dt - 1, gy = y + dy - 1;
        if (gt >= 0 && gt < TT && gy >= 0 && gy < HH) {
            float4 v = *(const float4*)&in[(((b * TT + gt) * HH + gy) * WW + x) * FF + c4 * 4];
            *(float4*)&sT[(rr * 42 + x + 1) * 40 + c4 * 4] = v;
        }
    }
    __syncthreads();

    const int x  = tid % 40;
    const int cg = tid / 40;
    float s = 0.0f;
#pragma unroll 1
    for (int rr = 0; rr < 9; rr++) {
#pragma unroll
        for (int dx = 0; dx < 3; dx++) {
            const float* ip = &sT[(rr * 42 + x + dx) * 40 + cg * 10];
            const float* wp = &sWc[(rr * 3 + dx) * 40 + cg * 10];
#pragma unroll
            for (int c = 0; c < 10; c++) s += ip[c] * wp[c];
        }
    }
    sP[cg * 40 + x] = s;
    __syncthreads();
    if (tid < 40) {
        float v = sP[tid] + sP[40 + tid] + sP[80 + tid] + sP[120 + tid] + b3[0];
        out[((b * TT + t) * HH + y) * WW + tid] = 1.0f / (1.0f + expf(-v));
    }
}

// ---------------------------------------------------------------------------
// kernel_launch: 35 wavefront launches + conv3d head. Graph-capturable.
// ---------------------------------------------------------------------------
extern "C" void kernel_launch(void* const* d_in, const int* in_sizes, int n_in,
                              void* d_out, int out_size)
{
    (void)in_sizes; (void)n_in; (void)out_size;

    const float* inp = (const float*)d_in[0];
    const float* W3  = (const float*)d_in[29];
    const float* b3  = (const float*)d_in[30];

    float *seqbase, *hbase, *cbase;
    cudaGetSymbolAddress((void**)&seqbase, g_seq);
    cudaGetSymbolAddress((void**)&hbase,   g_h);
    cudaGetSymbolAddress((void**)&cbase,   g_c);

    float* seqp[4];
    float* hp[4][2];
    float* cp[4];
    for (int l = 0; l < 4; l++) {
        seqp[l]  = seqbase + (size_t)l * SEQN;
        hp[l][0] = hbase + ((size_t)l * 2 + 0) * STN;
        hp[l][1] = hbase + ((size_t)l * 2 + 1) * STN;
        cp[l]    = cbase + (size_t)l * STN;
    }

    // CIN=40: sIn 3*42*80=10080 fl + sW4 10*160*4=6400 fl -> 65920 B (3 CTA/SM)
    const int SMEMW  = (3 * 42 * 80 + 10 * NG * 4) * 4;        // 65920 B
    const int smem3d = (9 * 42 * 40 + 27 * 40 + 4 * 40) * 4;   // 65440 B

    cudaFuncSetAttribute(wave_kernel,   cudaFuncAttributeMaxDynamicSharedMemorySize, SMEMW);
    cudaFuncSetAttribute(conv3d_kernel, cudaFuncAttributeMaxDynamicSharedMemorySize, smem3d);

    for (int wave = 0; wave < TT + 3; wave++) {
        int l0 = wave - (TT - 1); if (l0 < 0) l0 = 0;
        int l1 = wave < 3 ? wave : 3;

        WaveP P;
        for (int l = 0; l < 4; l++) {
            int t = wave - l;
            int tc = t < 0 ? 0 : (t > TT - 1 ? TT - 1 : t);
            P.in[l]   = (l == 0) ? inp : seqp[l - 1];
            P.out[l]  = seqp[l];
            P.hin[l]  = hp[l][tc & 1];
            P.hout[l] = hp[l][(tc + 1) & 1];
            P.c[l]    = cp[l];
            P.Wx[l]   = (const float*)d_in[1 + 7 * l];
            P.Wh[l]   = (const float*)d_in[2 + 7 * l];
            P.bias[l] = (const float*)d_in[3 + 7 * l];
            P.g[l]    = (const float*)d_in[4 + 7 * l];
            P.be[l]   = (const float*)d_in[5 + 7 * l];
            P.mu[l]   = (const float*)d_in[6 + 7 * l];
            P.v[l]    = (const float*)d_in[7 + 7 * l];
        }
        P.wave = wave;
        P.l0   = l0;

        wave_kernel<<<dim3(HH, BB, l1 - l0 + 1), NT, SMEMW>>>(P);
    }

    conv3d_kernel<<<dim3(HH, TT, BB), 160, smem3d>>>(seqp[3], W3, b3, (float*)d_out);
}

// round 14
// speedup vs baseline: 1.2880x; 1.1443x over previous
#include <cuda_runtime.h>
#include <stdint.h>
#include <math.h>

// Problem constants
#define BB 16
#define TT 32
#define HH 40
#define WW 40
#define FF 40
#define NG 160              // 4*F gate channels
#define NT 128              // threads per block
#define SEQN (BB*TT*HH*WW*FF)
#define STN  (BB*HH*WW*FF)

// ---------------------------------------------------------------------------
// Static device scratch.
// ---------------------------------------------------------------------------
__device__ float g_seq[4][SEQN];
__device__ float g_h[4][2][STN];
__device__ float g_c[4][STN];
// Pre-formatted quad-interleaved weights: [layer][tap][quad<20][chan 160] float4
__device__ float4 g_wq[4 * 9 * 20 * NG];

__device__ __forceinline__ float hsig(float x) {
    return fminf(fmaxf(0.2f * x + 0.5f, 0.0f), 1.0f);
}

__device__ __forceinline__ unsigned long long packf2(float lo, float hi) {
    unsigned long long r;
    asm("mov.b64 %0, {%1, %2};" : "=l"(r) : "f"(lo), "f"(hi));
    return r;
}
__device__ __forceinline__ float2 unpackf2(unsigned long long v) {
    float2 r;
    asm("mov.b64 {%0, %1}, %2;" : "=f"(r.x), "=f"(r.y) : "l"(v));
    return r;
}
__device__ __forceinline__ void fma2(unsigned long long& d,
                                     unsigned long long a, unsigned long long b) {
    asm("fma.rn.f32x2 %0, %1, %2, %0;" : "+l"(d) : "l"(a), "l"(b));
}

// ---------------------------------------------------------------------------
// Weight prep: gather Wx/Wh into quad-interleaved float4 rows with zero padding
// so per-chunk staging is one contiguous cp.async block.
// layer 0: CIN=1, HOFF=4, C2P=44 -> quads 0..10 data, 11..19 zero
// layer 1-3: CIN=40, HOFF=40, C2P=80 -> quads 0..19 data
// ---------------------------------------------------------------------------
struct PrepP { const float* Wx[4]; const float* Wh[4]; };

__global__ void prep_weights(PrepP P)
{
    int idx = blockIdx.x * 256 + threadIdx.x;
    if (idx >= 4 * 9 * 20 * NG) return;
    int c   = idx % NG;
    int q   = (idx / NG) % 20;
    int tap = (idx / (NG * 20)) % 9;
    int l   = idx / (NG * 20 * 9);
    int CIN  = (l == 0) ? 1 : 40;
    int HOFF = (l == 0) ? 4 : 40;
    int C2P  = HOFF + 40;
    const float* wx = P.Wx[l] + tap * CIN * NG;
    const float* wh = P.Wh[l] + tap * FF * NG;
    float w[4];
#pragma unroll
    for (int u = 0; u < 4; u++) {
        int kk = 4 * q + u;
        w[u] = (kk < CIN) ? wx[kk * NG + c]
             : (kk >= HOFF && kk < C2P) ? wh[(kk - HOFF) * NG + c] : 0.0f;
    }
    g_wq[idx] = make_float4(w[0], w[1], w[2], w[3]);
}

// ---------------------------------------------------------------------------
// One ConvLSTM timestep tile for one (layer, t): block = one image row (b,y).
// GEMM: M=40 px, N=160 gates, K=9*C2P (x/h merged, zero-padded).
// 128 threads: warp = 10 pixels, lane = 5 channels.  f32x2 acc over (even,odd) k.
//   A: LDS.128 per pixel per quad (warp-broadcast)
//   B: LDS.128 per channel per quad (quad-interleaved, cp.async staged)
// Weight chunks (CQ quads) double-buffered via cp.async -> staging fully hidden.
// SMEM (CIN=40): sIn 40336B + 2*12800B = 65936B -> 3 CTAs/SM.
// ---------------------------------------------------------------------------
template <int CIN>
__device__ __forceinline__ void lstm_tile(
    const float* __restrict__ xseq,   // [B,T,H,W,CIN]
    const float* __restrict__ hin,    // [B,H,W,F]
    float* __restrict__ hout,         // [B,H,W,F]
    float* __restrict__ cst,          // [B,H,W,F] in/out
    const float4* __restrict__ wq,    // [9][20][NG] quad-interleaved
    const float* __restrict__ bias,   // [160]
    const float* __restrict__ bng, const float* __restrict__ bnb,
    const float* __restrict__ bnm, const float* __restrict__ bnv,
    float* __restrict__ yout,         // [B,T,H,W,F]
    int t, int first)
{
    constexpr int HOFF  = (CIN + 3) & ~3;   // h channels start (4 or 40)
    constexpr int C2P   = HOFF + FF;        // padded concat channels (44 or 80)
    constexpr int INROW = 42;               // 40 + halo
    constexpr int CQ    = (CIN == 1) ? 4 : 5;    // quads per staged chunk
    constexpr int NCH   = (CIN == 1) ? 3 : 4;    // chunks per tap (12 / 20 quads)
    constexpr int SINSZ = 3 * INROW * C2P + 4;   // +4 floats: pad for quad-11 OOB (x0 weights)

    extern __shared__ float smem[];
    float* sIn = smem;                    // [3][INROW][C2P] (+4 pad)
    float* sW4 = smem + SINSZ;            // 2 x [CQ][NG] float4

    const int tid = threadIdx.x;
    const int y   = blockIdx.x;
    const int b   = blockIdx.y;
    const int n   = tid & 31;             // base output channel
    const int mt  = tid >> 5;             // warp -> pixels mt*10 .. mt*10+9

    unsigned int sW4_u32;
    asm("{ .reg .u64 t0; cvta.to.shared.u64 t0, %1; cvt.u32.u64 %0, t0; }"
        : "=r"(sW4_u32) : "l"(sW4));

    auto stage = [&](int parity, const float4* gsrc) {
        unsigned int dst = sW4_u32 + parity * (CQ * NG * 16);
        for (int p = tid; p < CQ * NG; p += NT)
            asm volatile("cp.async.cg.shared.global [%0], [%1], 16;"
                         :: "r"(dst + p * 16), "l"(gsrc + p) : "memory");
        asm volatile("cp.async.commit_group;" ::: "memory");
    };

    // kick off first weight chunk immediately (independent of sIn fill)
    stage(0, wq);

    // ---- zero input tile (halo + padding) ----
    for (int i = tid; i < SINSZ; i += NT) sIn[i] = 0.0f;
    __syncthreads();

    // ---- fill x part ----
    if (CIN == 1) {
        for (int i = tid; i < 3 * WW; i += NT) {
            int r = i / WW, x = i % WW;
            int gy = y + r - 1;
            if (gy >= 0 && gy < HH)
                sIn[(r * INROW + x + 1) * C2P] =
                    xseq[((b * TT + t) * HH + gy) * WW + x];
        }
    } else {
        constexpr int NC4 = CIN / 4;
        for (int i = tid; i < 3 * WW * NC4; i += NT) {
            int c4 = i % NC4;
            int rest = i / NC4;
            int x = rest % WW, r = rest / WW;
            int gy = y + r - 1;
            if (gy >= 0 && gy < HH) {
                float4 v = *(const float4*)&xseq[(((b * TT + t) * HH + gy) * WW + x) * CIN + c4 * 4];
                *(float4*)&sIn[(r * INROW + x + 1) * C2P + c4 * 4] = v;
            }
        }
    }

    // ---- fill h part (h==0 at t==0: region stays zero) ----
    if (!first) {
        for (int i = tid; i < 3 * WW * (FF / 4); i += NT) {
            int c4 = i % (FF / 4);
            int rest = i / (FF / 4);
            int x = rest % WW, r = rest / WW;
            int gy = y + r - 1;
            if (gy >= 0 && gy < HH) {
                float4 v = *(const float4*)&hin[((b * HH + gy) * WW + x) * FF + c4 * 4];
                *(float4*)&sIn[(r * INROW + x + 1) * C2P + HOFF + c4 * 4] = v;
            }
        }
    }

    // ---- accumulators = (bias, 0): lo = even-k sum, hi = odd-k sum ----
    unsigned long long acc[10][5];
#pragma unroll
    for (int j = 0; j < 5; j++) {
        unsigned long long bp = packf2(bias[n + 32 * j], 0.0f);
#pragma unroll
        for (int i = 0; i < 10; i++) acc[i][j] = bp;
    }

    // ---- main loop: 9 taps x NCH chunks, cp.async double-buffered weights ----
    int cnt = 0;
#pragma unroll 1
    for (int tap = 0; tap < 9; ++tap) {
        const int dy = tap / 3, dx = tap % 3;
        const float* abase0 = sIn + (dy * INROW + dx) * C2P + mt * 10 * C2P;

#pragma unroll 1
        for (int ch = 0; ch < NCH; ++ch) {
            asm volatile("cp.async.wait_group 0;" ::: "memory");
            __syncthreads();   // chunk(cnt) visible to all; prev compute done

            // prefetch next chunk into the other buffer
            int ntap = tap, nch = ch + 1;
            if (nch == NCH) { ntap++; nch = 0; }
            if (ntap < 9)
                stage((cnt + 1) & 1, wq + (ntap * 20 + nch * CQ) * NG);

            const ulonglong2* bb =
                (const ulonglong2*)(sW4 + (cnt & 1) * (CQ * NG * 4)) + n;
            const float* abase = abase0 + ch * CQ * 4;

#pragma unroll
            for (int q = 0; q < CQ; ++q) {
                ulonglong2 b2[5];
#pragma unroll
                for (int j = 0; j < 5; j++)
                    b2[j] = bb[q * NG + 32 * j];
#pragma unroll
                for (int i = 0; i < 10; i++) {
                    ulonglong2 a2 = *(const ulonglong2*)(abase + i * C2P + 4 * q);
#pragma unroll
                    for (int j = 0; j < 5; j++) fma2(acc[i][j], a2.x, b2[j].x);
#pragma unroll
                    for (int j = 0; j < 5; j++) fma2(acc[i][j], a2.y, b2[j].y);
                }
            }
            cnt++;
        }
    }

    // ---- z = lo + hi into smem base (sIn/sW4 dead), then gate math ----
    __syncthreads();
    float* sZ = smem;   // 40*160 floats = 25.6KB
#pragma unroll
    for (int i = 0; i < 10; i++)
#pragma unroll
        for (int j = 0; j < 5; j++) {
            float2 v = unpackf2(acc[i][j]);
            sZ[(mt * 10 + i) * NG + n + 32 * j] = v.x + v.y;
        }
    __syncthreads();

    for (int p = tid; p < WW * FF; p += NT) {
        int x = p / FF, c = p % FF;
        float zi = sZ[x * NG + c];
        float zf = sZ[x * NG + 40 + c];
        float zg = sZ[x * NG + 80 + c];
        float zo = sZ[x * NG + 120 + c];
        int off = ((b * HH + y) * WW + x) * FF + c;
        float cp = first ? 0.0f : cst[off];
        float cn = hsig(zf) * cp + hsig(zi) * tanhf(zg);
        float hn = hsig(zo) * tanhf(cn);
        cst[off]  = cn;
        hout[off] = hn;
        float s  = bng[c] * rsqrtf(bnv[c] + 1e-3f);
        float tt = bnb[c] - bnm[c] * s;
        yout[(((b * TT + t) * HH + y) * WW + x) * FF + c] = hn * s + tt;
    }
}

// ---------------------------------------------------------------------------
// Wavefront kernel: one launch covers all active (layer, t = wave - layer).
// ---------------------------------------------------------------------------
struct WaveP {
    const float*  in[4];
    float*        out[4];
    const float*  hin[4];
    float*        hout[4];
    float*        c[4];
    const float4* wq[4];
    const float*  bias[4];
    const float*  g[4]; const float* be[4]; const float* mu[4]; const float* v[4];
    int wave, l0;
};

__global__ __launch_bounds__(NT, 3) void wave_kernel(WaveP P)
{
    const int l = P.l0 + blockIdx.z;
    const int t = P.wave - l;
    const int first = (t == 0);
    if (l == 0)
        lstm_tile<1>(P.in[0], P.hin[0], P.hout[0], P.c[0],
                     P.wq[0], P.bias[0],
                     P.g[0], P.be[0], P.mu[0], P.v[0],
                     P.out[0], t, first);
    else
        lstm_tile<40>(P.in[l], P.hin[l], P.hout[l], P.c[l],
                      P.wq[l], P.bias[l],
                      P.g[l], P.be[l], P.mu[l], P.v[l],
                      P.out[l], t, first);
}

// ---------------------------------------------------------------------------
// Conv3D head: 3x3x3 over (T,H,W), 40 -> 1 channel, + sigmoid.
// ---------------------------------------------------------------------------
__global__ __launch_bounds__(160) void conv3d_kernel(
    const float* __restrict__ in,   // [B,T,H,W,F]
    const float* __restrict__ w3,   // [27*F]
    const float* __restrict__ b3,   // [1]
    float* __restrict__ out)        // [B,T,H,W]
{
    extern __shared__ float smem[];
    float* sT  = smem;                 // [9][42][40]
    float* sWc = smem + 9 * 42 * 40;   // [1080]
    float* sP  = sWc + 27 * 40;        // [4][40]

    const int tid = threadIdx.x;
    const int y = blockIdx.x, t = blockIdx.y, b = blockIdx.z;

    for (int i = tid; i < 9 * 42 * 40; i += 160) sT[i] = 0.0f;
    for (int i = tid; i < 27 * 40; i += 160) sWc[i] = w3[i];
    __syncthreads();

    for (int i = tid; i < 9 * 40 * 10; i += 160) {
        int c4 = i % 10;
        int rest = i / 10;
        int x = rest % 40;
        int rr = rest / 40;            // dt*3+dy
        int dt = rr / 3, dy = rr % 3;
        int gt = t + dt - 1, gy = y + dy - 1;
        if (gt >= 0 && gt < TT && gy >= 0 && gy < HH) {
            float4 v = *(const float4*)&in[(((b * TT + gt) * HH + gy) * WW + x) * FF + c4 * 4];
            *(float4*)&sT[(rr * 42 + x + 1) * 40 + c4 * 4] = v;
        }
    }
    __syncthreads();

    const int x  = tid % 40;
    const int cg = tid / 40;
    float s = 0.0f;
#pragma unroll 1
    for (int rr = 0; rr < 9; rr++) {
#pragma unroll
        for (int dx = 0; dx < 3; dx++) {
            const float* ip = &sT[(rr * 42 + x + dx) * 40 + cg * 10];
            const float* wp = &sWc[(rr * 3 + dx) * 40 + cg * 10];
#pragma unroll
            for (int c = 0; c < 10; c++) s += ip[c] * wp[c];
        }
    }
    sP[cg * 40 + x] = s;
    __syncthreads();
    if (tid < 40) {
        float v = sP[tid] + sP[40 + tid] + sP[80 + tid] + sP[120 + tid] + b3[0];
        out[((b * TT + t) * HH + y) * WW + tid] = 1.0f / (1.0f + expf(-v));
    }
}

// ---------------------------------------------------------------------------
// kernel_launch: weight prep + 35 wavefront launches + conv3d head.
// ---------------------------------------------------------------------------
extern "C" void kernel_launch(void* const* d_in, const int* in_sizes, int n_in,
                              void* d_out, int out_size)
{
    (void)in_sizes; (void)n_in; (void)out_size;

    const float* inp = (const float*)d_in[0];
    const float* W3  = (const float*)d_in[29];
    const float* b3  = (const float*)d_in[30];

    float *seqbase, *hbase, *cbase;
    float4* wqbase;
    cudaGetSymbolAddress((void**)&seqbase, g_seq);
    cudaGetSymbolAddress((void**)&hbase,   g_h);
    cudaGetSymbolAddress((void**)&cbase,   g_c);
    cudaGetSymbolAddress((void**)&wqbase,  g_wq);

    float* seqp[4];
    float* hp[4][2];
    float* cp[4];
    for (int l = 0; l < 4; l++) {
        seqp[l]  = seqbase + (size_t)l * SEQN;
        hp[l][0] = hbase + ((size_t)l * 2 + 0) * STN;
        hp[l][1] = hbase + ((size_t)l * 2 + 1) * STN;
        cp[l]    = cbase + (size_t)l * STN;
    }

    // ---- weight prep (runs every replay; deterministic) ----
    PrepP PP;
    for (int l = 0; l < 4; l++) {
        PP.Wx[l] = (const float*)d_in[1 + 7 * l];
        PP.Wh[l] = (const float*)d_in[2 + 7 * l];
    }
    prep_weights<<<(4 * 9 * 20 * NG + 255) / 256, 256>>>(PP);

    // smem: sIn (3*42*80+4)*4 = 40336 + 2*5*160*16 = 25600 -> 65936 B
    const int SMEMW  = (3 * 42 * 80 + 4) * 4 + 2 * 5 * NG * 16;
    const int smem3d = (9 * 42 * 40 + 27 * 40 + 4 * 40) * 4;

    cudaFuncSetAttribute(wave_kernel,   cudaFuncAttributeMaxDynamicSharedMemorySize, SMEMW);
    cudaFuncSetAttribute(conv3d_kernel, cudaFuncAttributeMaxDynamicSharedMemorySize, smem3d);

    for (int wave = 0; wave < TT + 3; wave++) {
        int l0 = wave - (TT - 1); if (l0 < 0) l0 = 0;
        int l1 = wave < 3 ? wave : 3;

        WaveP P;
        for (int l = 0; l < 4; l++) {
            int t = wave - l;
            int tc = t < 0 ? 0 : (t > TT - 1 ? TT - 1 : t);
            P.in[l]   = (l == 0) ? inp : seqp[l - 1];
            P.out[l]  = seqp[l];
            P.hin[l]  = hp[l][tc & 1];
            P.hout[l] = hp[l][(tc + 1) & 1];
            P.c[l]    = cp[l];
            P.wq[l]   = wqbase + (size_t)l * 9 * 20 * NG;
            P.bias[l] = (const float*)d_in[3 + 7 * l];
            P.g[l]    = (const float*)d_in[4 + 7 * l];
            P.be[l]   = (const float*)d_in[5 + 7 * l];
            P.mu[l]   = (const float*)d_in[6 + 7 * l];
            P.v[l]    = (const float*)d_in[7 + 7 * l];
        }
        P.wave = wave;
        P.l0   = l0;

        wave_kernel<<<dim3(HH, BB, l1 - l0 + 1), NT, SMEMW>>>(P);
    }

    conv3d_kernel<<<dim3(HH, TT, BB), 160, smem3d>>>(seqp[3], W3, b3, (float*)d_out);
}

// round 15
// speedup vs baseline: 1.2883x; 1.0003x over previous
#include <cuda_runtime.h>
#include <stdint.h>
#include <math.h>

// Problem constants
#define BB 16
#define TT 32
#define HH 40
#define WW 40
#define FF 40
#define NG 160              // 4*F gate channels
#define NT 128              // threads per block
#define SEQN (BB*TT*HH*WW*FF)
#define STN  (BB*HH*WW*FF)

// ---------------------------------------------------------------------------
// Static device scratch.
// ---------------------------------------------------------------------------
__device__ float g_seq[4][SEQN];
__device__ float g_h[4][2][STN];
__device__ float g_c[4][STN];
// Pre-formatted quad-interleaved weights: [layer][tap][quad<20][chan 160] float4
__device__ float4 g_wq[4 * 9 * 20 * NG];

__device__ __forceinline__ float hsig(float x) {
    return fminf(fmaxf(0.2f * x + 0.5f, 0.0f), 1.0f);
}

__device__ __forceinline__ unsigned long long packf2(float lo, float hi) {
    unsigned long long r;
    asm("mov.b64 %0, {%1, %2};" : "=l"(r) : "f"(lo), "f"(hi));
    return r;
}
__device__ __forceinline__ float2 unpackf2(unsigned long long v) {
    float2 r;
    asm("mov.b64 {%0, %1}, %2;" : "=f"(r.x), "=f"(r.y) : "l"(v));
    return r;
}
__device__ __forceinline__ void fma2(unsigned long long& d,
                                     unsigned long long a, unsigned long long b) {
    asm("fma.rn.f32x2 %0, %1, %2, %0;" : "+l"(d) : "l"(a), "l"(b));
}

// ---------------------------------------------------------------------------
// Weight prep: gather Wx/Wh into quad-interleaved float4 rows with zero padding
// so per-chunk staging is one contiguous cp.async block.
// layer 0: CIN=1, HOFF=4, C2P=44 -> quads 0..10 data, 11..19 zero
// layer 1-3: CIN=40, HOFF=40, C2P=80 -> quads 0..19 data
// ---------------------------------------------------------------------------
struct PrepP { const float* Wx[4]; const float* Wh[4]; };

__global__ void prep_weights(PrepP P)
{
    int idx = blockIdx.x * 256 + threadIdx.x;
    if (idx >= 4 * 9 * 20 * NG) return;
    int c   = idx % NG;
    int q   = (idx / NG) % 20;
    int tap = (idx / (NG * 20)) % 9;
    int l   = idx / (NG * 20 * 9);
    int CIN  = (l == 0) ? 1 : 40;
    int HOFF = (l == 0) ? 4 : 40;
    int C2P  = HOFF + 40;
    const float* wx = P.Wx[l] + tap * CIN * NG;
    const float* wh = P.Wh[l] + tap * FF * NG;
    float w[4];
#pragma unroll
    for (int u = 0; u < 4; u++) {
        int kk = 4 * q + u;
        w[u] = (kk < CIN) ? wx[kk * NG + c]
             : (kk >= HOFF && kk < C2P) ? wh[(kk - HOFF) * NG + c] : 0.0f;
    }
    g_wq[idx] = make_float4(w[0], w[1], w[2], w[3]);
}

// ---------------------------------------------------------------------------
// One ConvLSTM timestep tile for one (layer, t): block = one image row (b,y).
// GEMM: M=40 px, N=160 gates, K=9*C2P (x/h merged, zero-padded).
// 128 threads: warp = 10 pixels, lane = 5 channels.  f32x2 acc over (even,odd) k.
//   A: LDS.128 per pixel per quad (warp-broadcast)
//   B: LDS.128 per channel per quad (quad-interleaved, cp.async staged)
// Weight chunks (CQ quads) double-buffered via cp.async -> staging fully hidden.
// SMEM (CIN=40): sIn 40336B + 2*12800B = 65936B -> 3 CTAs/SM.
// ---------------------------------------------------------------------------
template <int CIN>
__device__ __forceinline__ void lstm_tile(
    const float* __restrict__ xseq,   // [B,T,H,W,CIN]
    const float* __restrict__ hin,    // [B,H,W,F]
    float* __restrict__ hout,         // [B,H,W,F]
    float* __restrict__ cst,          // [B,H,W,F] in/out
    const float4* __restrict__ wq,    // [9][20][NG] quad-interleaved
    const float* __restrict__ bias,   // [160]
    const float* __restrict__ bng, const float* __restrict__ bnb,
    const float* __restrict__ bnm, const float* __restrict__ bnv,
    float* __restrict__ yout,         // [B,T,H,W,F]
    int t, int first)
{
    constexpr int HOFF  = (CIN + 3) & ~3;   // h channels start (4 or 40)
    constexpr int C2P   = HOFF + FF;        // padded concat channels (44 or 80)
    constexpr int INROW = 42;               // 40 + halo
    constexpr int CQ    = (CIN == 1) ? 4 : 5;    // quads per staged chunk
    constexpr int NCH   = (CIN == 1) ? 3 : 4;    // chunks per tap (12 / 20 quads)
    constexpr int SINSZ = 3 * INROW * C2P + 4;   // +4 floats: pad for quad-11 OOB (x0 weights)

    extern __shared__ float smem[];
    float* sIn = smem;                    // [3][INROW][C2P] (+4 pad)
    float* sW4 = smem + SINSZ;            // 2 x [CQ][NG] float4

    const int tid = threadIdx.x;
    const int y   = blockIdx.x;
    const int b   = blockIdx.y;
    const int n   = tid & 31;             // base output channel
    const int mt  = tid >> 5;             // warp -> pixels mt*10 .. mt*10+9

    unsigned int sW4_u32;
    asm("{ .reg .u64 t0; cvta.to.shared.u64 t0, %1; cvt.u32.u64 %0, t0; }"
        : "=r"(sW4_u32) : "l"(sW4));

    auto stage = [&](int parity, const float4* gsrc) {
        unsigned int dst = sW4_u32 + parity * (CQ * NG * 16);
        for (int p = tid; p < CQ * NG; p += NT)
            asm volatile("cp.async.cg.shared.global [%0], [%1], 16;"
                         :: "r"(dst + p * 16), "l"(gsrc + p) : "memory");
        asm volatile("cp.async.commit_group;" ::: "memory");
    };

    // kick off first weight chunk immediately (independent of sIn fill)
    stage(0, wq);

    // ---- zero input tile (halo + padding) ----
    for (int i = tid; i < SINSZ; i += NT) sIn[i] = 0.0f;
    __syncthreads();

    // ---- fill x part ----
    if (CIN == 1) {
        for (int i = tid; i < 3 * WW; i += NT) {
            int r = i / WW, x = i % WW;
            int gy = y + r - 1;
            if (gy >= 0 && gy < HH)
                sIn[(r * INROW + x + 1) * C2P] =
                    xseq[((b * TT + t) * HH + gy) * WW + x];
        }
    } else {
        constexpr int NC4 = CIN / 4;
        for (int i = tid; i < 3 * WW * NC4; i += NT) {
            int c4 = i % NC4;
            int rest = i / NC4;
            int x = rest % WW, r = rest / WW;
            int gy = y + r - 1;
            if (gy >= 0 && gy < HH) {
                float4 v = *(const float4*)&xseq[(((b * TT + t) * HH + gy) * WW + x) * CIN + c4 * 4];
                *(float4*)&sIn[(r * INROW + x + 1) * C2P + c4 * 4] = v;
            }
        }
    }

    // ---- fill h part (h==0 at t==0: region stays zero) ----
    if (!first) {
        for (int i = tid; i < 3 * WW * (FF / 4); i += NT) {
            int c4 = i % (FF / 4);
            int rest = i / (FF / 4);
            int x = rest % WW, r = rest / WW;
            int gy = y + r - 1;
            if (gy >= 0 && gy < HH) {
                float4 v = *(const float4*)&hin[((b * HH + gy) * WW + x) * FF + c4 * 4];
                *(float4*)&sIn[(r * INROW + x + 1) * C2P + HOFF + c4 * 4] = v;
            }
        }
    }

    // ---- accumulators = (bias, 0): lo = even-k sum, hi = odd-k sum ----
    unsigned long long acc[10][5];
#pragma unroll
    for (int j = 0; j < 5; j++) {
        unsigned long long bp = packf2(bias[n + 32 * j], 0.0f);
#pragma unroll
        for (int i = 0; i < 10; i++) acc[i][j] = bp;
    }

    // ---- main loop: 9 taps x NCH chunks, cp.async double-buffered weights ----
    int cnt = 0;
#pragma unroll 1
    for (int tap = 0; tap < 9; ++tap) {
        const int dy = tap / 3, dx = tap % 3;
        const float* abase0 = sIn + (dy * INROW + dx) * C2P + mt * 10 * C2P;

#pragma unroll 1
        for (int ch = 0; ch < NCH; ++ch) {
            asm volatile("cp.async.wait_group 0;" ::: "memory");
            __syncthreads();   // chunk(cnt) visible to all; prev compute done

            // prefetch next chunk into the other buffer
            int ntap = tap, nch = ch + 1;
            if (nch == NCH) { ntap++; nch = 0; }
            if (ntap < 9)
                stage((cnt + 1) & 1, wq + (ntap * 20 + nch * CQ) * NG);

            const ulonglong2* bb =
                (const ulonglong2*)(sW4 + (cnt & 1) * (CQ * NG * 4)) + n;
            const float* abase = abase0 + ch * CQ * 4;

#pragma unroll
            for (int q = 0; q < CQ; ++q) {
                ulonglong2 b2[5];
#pragma unroll
                for (int j = 0; j < 5; j++)
                    b2[j] = bb[q * NG + 32 * j];
#pragma unroll
                for (int i = 0; i < 10; i++) {
                    ulonglong2 a2 = *(const ulonglong2*)(abase + i * C2P + 4 * q);
#pragma unroll
                    for (int j = 0; j < 5; j++) fma2(acc[i][j], a2.x, b2[j].x);
#pragma unroll
                    for (int j = 0; j < 5; j++) fma2(acc[i][j], a2.y, b2[j].y);
                }
            }
            cnt++;
        }
    }

    // ---- z = lo + hi into smem base (sIn/sW4 dead), then gate math ----
    __syncthreads();
    float* sZ = smem;   // 40*160 floats = 25.6KB
#pragma unroll
    for (int i = 0; i < 10; i++)
#pragma unroll
        for (int j = 0; j < 5; j++) {
            float2 v = unpackf2(acc[i][j]);
            sZ[(mt * 10 + i) * NG + n + 32 * j] = v.x + v.y;
        }
    __syncthreads();

    for (int p = tid; p < WW * FF; p += NT) {
        int x = p / FF, c = p % FF;
        float zi = sZ[x * NG + c];
        float zf = sZ[x * NG + 40 + c];
        float zg = sZ[x * NG + 80 + c];
        float zo = sZ[x * NG + 120 + c];
        int off = ((b * HH + y) * WW + x) * FF + c;
        float cp = first ? 0.0f : cst[off];
        float cn = hsig(zf) * cp + hsig(zi) * tanhf(zg);
        float hn = hsig(zo) * tanhf(cn);
        cst[off]  = cn;
        hout[off] = hn;
        float s  = bng[c] * rsqrtf(bnv[c] + 1e-3f);
        float tt = bnb[c] - bnm[c] * s;
        yout[(((b * TT + t) * HH + y) * WW + x) * FF + c] = hn * s + tt;
    }
}

// ---------------------------------------------------------------------------
// Wavefront kernel: one launch covers all active (layer, t = wave - layer).
// ---------------------------------------------------------------------------
struct WaveP {
    const float*  in[4];
    float*        out[4];
    const float*  hin[4];
    float*        hout[4];
    float*        c[4];
    const float4* wq[4];
    const float*  bias[4];
    const float*  g[4]; const float* be[4]; const float* mu[4]; const float* v[4];
    int wave, l0;
};

__global__ __launch_bounds__(NT, 3) void wave_kernel(WaveP P)
{
    const int l = P.l0 + blockIdx.z;
    const int t = P.wave - l;
    const int first = (t == 0);
    if (l == 0)
        lstm_tile<1>(P.in[0], P.hin[0], P.hout[0], P.c[0],
                     P.wq[0], P.bias[0],
                     P.g[0], P.be[0], P.mu[0], P.v[0],
                     P.out[0], t, first);
    else
        lstm_tile<40>(P.in[l], P.hin[l], P.hout[l], P.c[l],
                      P.wq[l], P.bias[l],
                      P.g[l], P.be[l], P.mu[l], P.v[l],
                      P.out[l], t, first);
}

// ---------------------------------------------------------------------------
// Conv3D head: 3x3x3 over (T,H,W), 40 -> 1 channel, + sigmoid.
// ---------------------------------------------------------------------------
__global__ __launch_bounds__(160) void conv3d_kernel(
    const float* __restrict__ in,   // [B,T,H,W,F]
    const float* __restrict__ w3,   // [27*F]
    const float* __restrict__ b3,   // [1]
    float* __restrict__ out)        // [B,T,H,W]
{
    extern __shared__ float smem[];
    float* sT  = smem;                 // [9][42][40]
    float* sWc = smem + 9 * 42 * 40;   // [1080]
    float* sP  = sWc + 27 * 40;        // [4][40]

    const int tid = threadIdx.x;
    const int y = blockIdx.x, t = blockIdx.y, b = blockIdx.z;

    for (int i = tid; i < 9 * 42 * 40; i += 160) sT[i] = 0.0f;
    for (int i = tid; i < 27 * 40; i += 160) sWc[i] = w3[i];
    __syncthreads();

    for (int i = tid; i < 9 * 40 * 10; i += 160) {
        int c4 = i % 10;
        int rest = i / 10;
        int x = rest % 40;
        int rr = rest / 40;            // dt*3+dy
        int dt = rr / 3, dy = rr % 3;
        int gt = t + dt - 1, gy = y + dy - 1;
        if (gt >= 0 && gt < TT && gy >= 0 && gy < HH) {
            float4 v = *(const float4*)&in[(((b * TT + gt) * HH + gy) * WW + x) * FF + c4 * 4];
            *(float4*)&sT[(rr * 42 + x + 1) * 40 + c4 * 4] = v;
        }
    }
    __syncthreads();

    const int x  = tid % 40;
    const int cg = tid / 40;
    float s = 0.0f;
#pragma unroll 1
    for (int rr = 0; rr < 9; rr++) {
#pragma unroll
        for (int dx = 0; dx < 3; dx++) {
            const float* ip = &sT[(rr * 42 + x + dx) * 40 + cg * 10];
            const float* wp = &sWc[(rr * 3 + dx) * 40 + cg * 10];
#pragma unroll
            for (int c = 0; c < 10; c++) s += ip[c] * wp[c];
        }
    }
    sP[cg * 40 + x] = s;
    __syncthreads();
    if (tid < 40) {
        float v = sP[tid] + sP[40 + tid] + sP[80 + tid] + sP[120 + tid] + b3[0];
        out[((b * TT + t) * HH + y) * WW + tid] = 1.0f / (1.0f + expf(-v));
    }
}

// ---------------------------------------------------------------------------
// kernel_launch: weight prep + 35 wavefront launches + conv3d head.
// ---------------------------------------------------------------------------
extern "C" void kernel_launch(void* const* d_in, const int* in_sizes, int n_in,
                              void* d_out, int out_size)
{
    (void)in_sizes; (void)n_in; (void)out_size;

    const float* inp = (const float*)d_in[0];
    const float* W3  = (const float*)d_in[29];
    const float* b3  = (const float*)d_in[30];

    float *seqbase, *hbase, *cbase;
    float4* wqbase;
    cudaGetSymbolAddress((void**)&seqbase, g_seq);
    cudaGetSymbolAddress((void**)&hbase,   g_h);
    cudaGetSymbolAddress((void**)&cbase,   g_c);
    cudaGetSymbolAddress((void**)&wqbase,  g_wq);

    float* seqp[4];
    float* hp[4][2];
    float* cp[4];
    for (int l = 0; l < 4; l++) {
        seqp[l]  = seqbase + (size_t)l * SEQN;
        hp[l][0] = hbase + ((size_t)l * 2 + 0) * STN;
        hp[l][1] = hbase + ((size_t)l * 2 + 1) * STN;
        cp[l]    = cbase + (size_t)l * STN;
    }

    // ---- weight prep (runs every replay; deterministic) ----
    PrepP PP;
    for (int l = 0; l < 4; l++) {
        PP.Wx[l] = (const float*)d_in[1 + 7 * l];
        PP.Wh[l] = (const float*)d_in[2 + 7 * l];
    }
    prep_weights<<<(4 * 9 * 20 * NG + 255) / 256, 256>>>(PP);

    // smem: sIn (3*42*80+4)*4 = 40336 + 2*5*160*16 = 25600 -> 65936 B
    const int SMEMW  = (3 * 42 * 80 + 4) * 4 + 2 * 5 * NG * 16;
    const int smem3d = (9 * 42 * 40 + 27 * 40 + 4 * 40) * 4;

    cudaFuncSetAttribute(wave_kernel,   cudaFuncAttributeMaxDynamicSharedMemorySize, SMEMW);
    cudaFuncSetAttribute(conv3d_kernel, cudaFuncAttributeMaxDynamicSharedMemorySize, smem3d);

    for (int wave = 0; wave < TT + 3; wave++) {
        int l0 = wave - (TT - 1); if (l0 < 0) l0 = 0;
        int l1 = wave < 3 ? wave : 3;

        WaveP P;
        for (int l = 0; l < 4; l++) {
            int t = wave - l;
            int tc = t < 0 ? 0 : (t > TT - 1 ? TT - 1 : t);
            P.in[l]   = (l == 0) ? inp : seqp[l - 1];
            P.out[l]  = seqp[l];
            P.hin[l]  = hp[l][tc & 1];
            P.hout[l] = hp[l][(tc + 1) & 1];
            P.c[l]    = cp[l];
            P.wq[l]   = wqbase + (size_t)l * 9 * 20 * NG;
            P.bias[l] = (const float*)d_in[3 + 7 * l];
            P.g[l]    = (const float*)d_in[4 + 7 * l];
            P.be[l]   = (const float*)d_in[5 + 7 * l];
            P.mu[l]   = (const float*)d_in[6 + 7 * l];
            P.v[l]    = (const float*)d_in[7 + 7 * l];
        }
        P.wave = wave;
        P.l0   = l0;

        wave_kernel<<<dim3(HH, BB, l1 - l0 + 1), NT, SMEMW>>>(P);
    }

    conv3d_kernel<<<dim3(HH, TT, BB), 160, smem3d>>>(seqp[3], W3, b3, (float*)d_out);
}